// round 2
// baseline (speedup 1.0000x reference)
#include <cuda_runtime.h>
#include <cstdint>

#define NB   16
#define NN   20000
#define NE   640000
#define NREG 2000
#define DIN  128
#define FF   32

// ---------------- scratch (device globals; no allocation allowed) ----------
__device__ float    g_h[(size_t)NB * NN * FF];       // 40.96 MB
__device__ float    g_rep[(size_t)NB * NN * FF];     // 40.96 MB
__device__ float    g_asrc[NB * NN];
__device__ float    g_adst[NB * NN];
__device__ int      g_src32[NE];
__device__ int      g_dst32[NE];
__device__ int      g_cnt[NN];
__device__ int      g_off[NN + 1];
__device__ int      g_cur[NN];
__device__ unsigned g_sorted[NE];                    // (src<<20)|eid
__device__ int      g_soff[NREG + 1];
__device__ float    g_mean[NB];
__device__ float    g_c;
__device__ int      g_is64;

// ---------------- dtype detection ------------------------------------------
// If edge indices are int64 (values < 2^31, non-negative), every odd int32
// word of the buffer is 0. For real int32 random data in [0, 20000), 512
// consecutive odd words being all zero has probability ~0.
__global__ void k_detect(const int* __restrict__ p) {
    int any = 0;
    for (int i = threadIdx.x; i < 1024; i += 32)
        if ((i & 1) && p[i] != 0) any = 1;
    #pragma unroll
    for (int o = 16; o; o >>= 1) any |= __shfl_xor_sync(0xFFFFFFFFu, any, o);
    if (threadIdx.x == 0) g_is64 = !any;
}

// ---------------- small prep kernels ---------------------------------------
__global__ void k_zero() {
    int i = blockIdx.x * blockDim.x + threadIdx.x;
    if (i < NN) g_cnt[i] = 0;
    if (i < NB) g_mean[i] = 0.f;
}

__global__ void k_scalar(const float* __restrict__ lin_edge,
                         const float* __restrict__ att_edge) {
    int lane = threadIdx.x;
    float p = lin_edge[lane] * att_edge[lane];
    #pragma unroll
    for (int o = 16; o; o >>= 1) p += __shfl_xor_sync(0xFFFFFFFFu, p, o);
    if (lane == 0) g_c = p;
}

__global__ void k_convert(const void* __restrict__ srcv,
                          const void* __restrict__ dstv) {
    int e = blockIdx.x * blockDim.x + threadIdx.x;
    if (e >= NE) return;
    int s, d;
    if (g_is64) {
        s = (int)((const long long*)srcv)[e];
        d = (int)((const long long*)dstv)[e];
    } else {
        s = ((const int*)srcv)[e];
        d = ((const int*)dstv)[e];
    }
    g_src32[e] = s;
    g_dst32[e] = d;
    atomicAdd(&g_cnt[d], 1);
}

// single-block exclusive scan over 20000 counts (chunk=20 per thread)
__global__ void k_scan() {
    __shared__ int tot[1024];
    int t = threadIdx.x;
    int base = t * 20;
    int loc[20];
    int run = 0;
    #pragma unroll
    for (int i = 0; i < 20; i++) {
        int idx = base + i;
        int v = (idx < NN) ? g_cnt[idx] : 0;
        loc[i] = run;
        run += v;
    }
    tot[t] = run;
    __syncthreads();
    for (int off = 1; off < 1024; off <<= 1) {
        int v = (t >= off) ? tot[t - off] : 0;
        __syncthreads();
        tot[t] += v;
        __syncthreads();
    }
    int excl = tot[t] - run;
    #pragma unroll
    for (int i = 0; i < 20; i++) {
        int idx = base + i;
        if (idx < NN) {
            int o = excl + loc[i];
            g_off[idx] = o;
            g_cur[idx] = o;
        }
    }
    if (t == 1023) g_off[NN] = tot[1023];
}

__global__ void k_scatter() {
    int e = blockIdx.x * blockDim.x + threadIdx.x;
    if (e >= NE) return;
    int d = g_dst32[e];
    int pos = atomicAdd(&g_cur[d], 1);
    g_sorted[pos] = ((unsigned)g_src32[e] << 20) | (unsigned)e;
}

__global__ void k_mean(const float* __restrict__ eattr) {
    int b = blockIdx.y;
    const float* p = eattr + (size_t)b * NE;
    float s = 0.f;
    for (int i = blockIdx.x * blockDim.x + threadIdx.x; i < NE;
         i += gridDim.x * blockDim.x)
        s += p[i];
    __shared__ float sm[8];
    int lane = threadIdx.x & 31, wid = threadIdx.x >> 5;
    #pragma unroll
    for (int o = 16; o; o >>= 1) s += __shfl_xor_sync(0xFFFFFFFFu, s, o);
    if (lane == 0) sm[wid] = s;
    __syncthreads();
    if (wid == 0) {
        s = (lane < 8) ? sm[lane] : 0.f;
        #pragma unroll
        for (int o = 4; o; o >>= 1) s += __shfl_xor_sync(0xFFFFFFFFu, s, o);
        if (lane == 0) atomicAdd(&g_mean[b], s);
    }
}

__global__ void k_soff() {
    int r = blockIdx.x * blockDim.x + threadIdx.x;
    if (r > NREG) return;
    int lo = 0, hi = NE;
    while (lo < hi) {
        int mid = (lo + hi) >> 1;
        if (g_src32[mid] < r) lo = mid + 1; else hi = mid;
    }
    g_soff[r] = lo;
}

// ---------------- GEMM: h = x @ W, a_src = h.att_src, a_dst = h.att_dst ----
__global__ void __launch_bounds__(256, 6)
k_gemm(const float* __restrict__ x, const float* __restrict__ W,
       const float* __restrict__ attS, const float* __restrict__ attD) {
    __shared__ float Wt[32 * 132];       // Wt[f][k], stride 132 (16B-aligned)
    __shared__ float xs[8][4][128];      // per-warp 4 rows
    int tid = threadIdx.x, wid = tid >> 5, lane = tid & 31;

    for (int i = tid; i < DIN * FF; i += 256) {
        int k = i >> 5, f = i & 31;
        Wt[f * 132 + k] = W[i];
    }
    __syncthreads();

    float aS = attS[lane], aD = attD[lane];
    size_t rowBase = (size_t)blockIdx.x * 32 + (size_t)wid * 4;

    const float4* xg = (const float4*)(x + rowBase * DIN);
    float4* xw = (float4*)xs[wid];
    #pragma unroll
    for (int i = 0; i < 4; i++) xw[lane + 32 * i] = xg[lane + 32 * i];
    __syncwarp();

    float acc[4] = {0.f, 0.f, 0.f, 0.f};
    #pragma unroll 8
    for (int kc = 0; kc < 32; kc++) {
        float4 wf = *(const float4*)&Wt[lane * 132 + kc * 4];
        #pragma unroll
        for (int r = 0; r < 4; r++) {
            float4 xv = *(const float4*)&xs[wid][r][kc * 4];
            acc[r] = fmaf(xv.x, wf.x, acc[r]);
            acc[r] = fmaf(xv.y, wf.y, acc[r]);
            acc[r] = fmaf(xv.z, wf.z, acc[r]);
            acc[r] = fmaf(xv.w, wf.w, acc[r]);
        }
    }

    float* hp = g_h + rowBase * FF;
    #pragma unroll
    for (int r = 0; r < 4; r++) {
        hp[r * FF + lane] = acc[r];
        float vs = acc[r] * aS, vd = acc[r] * aD;
        #pragma unroll
        for (int o = 16; o; o >>= 1) {
            vs += __shfl_xor_sync(0xFFFFFFFFu, vs, o);
            vd += __shfl_xor_sync(0xFFFFFFFFu, vd, o);
        }
        if (lane == 0) {
            g_asrc[rowBase + r] = vs;
            g_adst[rowBase + r] = vd;
        }
    }
}

// ---------------- per-(b,dst) segment: softmax + weighted aggregation ------
__device__ __forceinline__ float lrelu(float a) {
    return fmaxf(a, 0.f) + 0.2f * fminf(a, 0.f);
}

__global__ void __launch_bounds__(256, 6)
k_edge(const float* __restrict__ eattr, const float* __restrict__ bias) {
    int wid = threadIdx.x >> 5, lane = threadIdx.x & 31;
    int seg = blockIdx.x * 8 + wid;                 // 0 .. NB*NN-1
    int b = seg / NN, d = seg - b * NN;

    const float* asb = g_asrc + b * NN;
    const float* eab = eattr + (size_t)b * NE;
    float ad = g_adst[b * NN + d];
    float c = g_c;
    float meanb = g_mean[b] * (1.0f / NE);
    int lo = g_off[d], hi = g_off[d + 1];

    // pass 1: denominator (lanes parallel over edges)
    float s = 0.f;
    for (int i = lo + lane; i < hi; i += 32) {
        unsigned p = g_sorted[i];
        int sA = p >> 20;
        int eid = p & 0xFFFFFu;
        float a = lrelu(asb[sA] + ad + c * __ldg(&eab[eid]));
        s += __expf(a);
    }
    #pragma unroll
    for (int o = 16; o; o >>= 1) s += __shfl_xor_sync(0xFFFFFFFFu, s, o);
    float asl = lrelu(asb[d] + ad + c * meanb);     // self-loop
    float exs = __expf(asl);
    s += exs;

    // pass 2: aggregation (lane = feature)
    const float* hb = g_h + (size_t)b * NN * FF;
    float acc = exs * hb[(size_t)d * FF + lane];
    for (int i = lo; i < hi; ++i) {
        unsigned p = g_sorted[i];
        int sA = p >> 20;
        int eid = p & 0xFFFFFu;
        float a = lrelu(asb[sA] + ad + c * __ldg(&eab[eid]));
        acc = fmaf(__expf(a), hb[(size_t)sA * FF + lane], acc);
    }
    g_rep[((size_t)b * NN + d) * FF + lane] = acc / s + bias[lane];
}

// ---------------- regulon pooling: out[b,r] = rep[b,r] + sum rep[b,dst] ----
__global__ void __launch_bounds__(256, 6)
k_pool(float* __restrict__ out) {
    int wid = threadIdx.x >> 5, lane = threadIdx.x & 31;
    int seg = blockIdx.x * 8 + wid;                 // 0 .. NB*NREG-1
    int b = seg / NREG, r = seg - b * NREG;
    int lo = g_soff[r], hi = g_soff[r + 1];
    const float* repb = g_rep + (size_t)b * NN * FF;

    float a0 = repb[(size_t)r * FF + lane];
    float a1 = 0.f, a2 = 0.f, a3 = 0.f;
    for (int e0 = lo; e0 < hi; e0 += 32) {
        int rem = hi - e0;
        int m = rem < 32 ? rem : 32;
        int myd = (lane < m) ? g_dst32[e0 + lane] : 0;
        int j = 0;
        for (; j + 4 <= m; j += 4) {
            int d0 = __shfl_sync(0xFFFFFFFFu, myd, j);
            int d1 = __shfl_sync(0xFFFFFFFFu, myd, j + 1);
            int d2 = __shfl_sync(0xFFFFFFFFu, myd, j + 2);
            int d3 = __shfl_sync(0xFFFFFFFFu, myd, j + 3);
            a0 += repb[(size_t)d0 * FF + lane];
            a1 += repb[(size_t)d1 * FF + lane];
            a2 += repb[(size_t)d2 * FF + lane];
            a3 += repb[(size_t)d3 * FF + lane];
        }
        for (; j < m; ++j) {
            int dd = __shfl_sync(0xFFFFFFFFu, myd, j);
            a0 += repb[(size_t)dd * FF + lane];
        }
    }
    out[((size_t)b * NREG + r) * FF + lane] = (a0 + a1) + (a2 + a3);
}

// ---------------- launch ---------------------------------------------------
extern "C" void kernel_launch(void* const* d_in, const int* in_sizes, int n_in,
                              void* d_out, int out_size) {
    const float* x        = (const float*)d_in[0];
    const float* edgeattr = (const float*)d_in[1];
    const float* W        = (const float*)d_in[2];
    const float* att_src  = (const float*)d_in[3];
    const float* att_dst  = (const float*)d_in[4];
    const float* lin_edge = (const float*)d_in[5];
    const float* att_edge = (const float*)d_in[6];
    const float* bias     = (const float*)d_in[7];
    const void*  esrc     = d_in[8];
    const void*  edst     = d_in[9];
    float* out = (float*)d_out;

    k_detect<<<1, 32>>>((const int*)edst);
    k_zero<<<(NN + 255) / 256, 256>>>();
    k_scalar<<<1, 32>>>(lin_edge, att_edge);
    k_convert<<<NE / 256, 256>>>(esrc, edst);
    k_scan<<<1, 1024>>>();
    k_scatter<<<NE / 256, 256>>>();
    k_mean<<<dim3(64, NB), 256>>>(edgeattr);
    k_soff<<<(NREG + 1 + 255) / 256, 256>>>();
    k_gemm<<<(NB * NN) / 32, 256>>>(x, W, att_src, att_dst);
    k_edge<<<(NB * NN) / 8, 256>>>(edgeattr, bias);
    k_pool<<<(NB * NREG) / 8, 256>>>(out);
}

// round 3
// speedup vs baseline: 1.2027x; 1.2027x over previous
#include <cuda_runtime.h>
#include <cstdint>

#define NB   16
#define NN   20000
#define NE   640000
#define NREG 2000
#define DIN  128
#define FF   32

// ---------------- scratch (device globals; no allocation allowed) ----------
__device__ float    g_h[(size_t)NB * NN * FF];       // 40.96 MB
__device__ float    g_rep[(size_t)NB * NN * FF];     // 40.96 MB
__device__ float    g_asrc[NB * NN];
__device__ float    g_adst[NB * NN];
__device__ int      g_src32[NE];
__device__ int      g_dst32[NE];
__device__ int      g_cnt[NN];
__device__ int      g_off[NN + 1];
__device__ int      g_cur[NN];
__device__ unsigned g_sorted[NE];                    // (src<<20)|eid
__device__ int      g_soff[NREG + 1];
__device__ float    g_meanpart[NB][8];
__device__ float    g_mean[NB];
__device__ float    g_c;
__device__ int      g_is64;

// ---------------- f32x2 helpers ---------------------------------------------
__device__ __forceinline__ void fma2(unsigned long long& d,
                                     unsigned long long a,
                                     unsigned long long b) {
    asm("fma.rn.f32x2 %0, %1, %2, %0;" : "+l"(d) : "l"(a), "l"(b));
}
__device__ __forceinline__ unsigned long long dup2(float w) {
    unsigned long long r;
    asm("mov.b64 %0, {%1, %1};" : "=l"(r) : "f"(w));
    return r;
}
__device__ __forceinline__ void unpack2(unsigned long long v, float& lo, float& hi) {
    asm("mov.b64 {%0, %1}, %2;" : "=f"(lo), "=f"(hi) : "l"(v));
}

// ---------------- prep: zero cnt, mean partials, scalar c, dtype detect -----
// grid (8, 16), block 256. y = batch for mean partial sums.
__global__ void k_prep(const float* __restrict__ eattr,
                       const float* __restrict__ lin_edge,
                       const float* __restrict__ att_edge,
                       const int* __restrict__ edge_raw) {
    int tid = threadIdx.x, bx = blockIdx.x, by = blockIdx.y;
    int lane = tid & 31, wid = tid >> 5;

    // zero counters (flattened over all blocks)
    int id = (by * 8 + bx) * 256 + tid;
    if (id < NN) g_cnt[id] = 0;

    if (bx == 0 && by == 0) {
        if (wid == 0) {
            // dtype detect: int64 values < 2^31 => all odd int32 words zero
            int any = 0;
            for (int i = lane; i < 1024; i += 32)
                if ((i & 1) && edge_raw[i] != 0) any = 1;
            #pragma unroll
            for (int o = 16; o; o >>= 1) any |= __shfl_xor_sync(0xFFFFFFFFu, any, o);
            if (lane == 0) g_is64 = !any;
        } else if (wid == 1) {
            float p = lin_edge[lane] * att_edge[lane];
            #pragma unroll
            for (int o = 16; o; o >>= 1) p += __shfl_xor_sync(0xFFFFFFFFu, p, o);
            if (lane == 0) g_c = p;
        }
    }

    // mean partial for batch by
    const float* p = eattr + (size_t)by * NE;
    float s = 0.f;
    for (int i = bx * 256 + tid; i < NE; i += 8 * 256) s += p[i];
    __shared__ float sm[8];
    #pragma unroll
    for (int o = 16; o; o >>= 1) s += __shfl_xor_sync(0xFFFFFFFFu, s, o);
    if (lane == 0) sm[wid] = s;
    __syncthreads();
    if (wid == 0) {
        s = (lane < 8) ? sm[lane] : 0.f;
        #pragma unroll
        for (int o = 4; o; o >>= 1) s += __shfl_xor_sync(0xFFFFFFFFu, s, o);
        if (lane == 0) g_meanpart[by][bx] = s;
    }
}

// ---------------- convert indices + histogram -------------------------------
__global__ void k_convert(const void* __restrict__ srcv,
                          const void* __restrict__ dstv) {
    int e = blockIdx.x * blockDim.x + threadIdx.x;
    if (e >= NE) return;
    int s, d;
    if (g_is64) {
        s = (int)((const long long*)srcv)[e];
        d = (int)((const long long*)dstv)[e];
    } else {
        s = ((const int*)srcv)[e];
        d = ((const int*)dstv)[e];
    }
    g_src32[e] = s;
    g_dst32[e] = d;
    atomicAdd(&g_cnt[d], 1);
}

// ---------------- scan + soff + mean finalize (single block, 1024 thr) ------
__global__ void k_scan() {
    __shared__ int tot[1024];
    int t = threadIdx.x;
    int base = t * 20;
    int loc[20];
    int run = 0;
    #pragma unroll
    for (int i = 0; i < 20; i++) {
        int idx = base + i;
        int v = (idx < NN) ? g_cnt[idx] : 0;
        loc[i] = run;
        run += v;
    }
    tot[t] = run;
    __syncthreads();
    for (int off = 1; off < 1024; off <<= 1) {
        int v = (t >= off) ? tot[t - off] : 0;
        __syncthreads();
        tot[t] += v;
        __syncthreads();
    }
    int excl = tot[t] - run;
    #pragma unroll
    for (int i = 0; i < 20; i++) {
        int idx = base + i;
        if (idx < NN) {
            int o = excl + loc[i];
            g_off[idx] = o;
            g_cur[idx] = o;
        }
    }
    if (t == 1023) g_off[NN] = tot[1023];

    // soff: binary search of regulon boundaries in sorted g_src32
    for (int r = t; r <= NREG; r += 1024) {
        int lo = 0, hi = NE;
        while (lo < hi) {
            int mid = (lo + hi) >> 1;
            if (g_src32[mid] < r) lo = mid + 1; else hi = mid;
        }
        g_soff[r] = lo;
    }

    // mean finalize
    if (t < NB) {
        float s = 0.f;
        #pragma unroll
        for (int i = 0; i < 8; i++) s += g_meanpart[t][i];
        g_mean[t] = s * (1.0f / NE);
    }
}

__global__ void k_scatter() {
    int e = blockIdx.x * blockDim.x + threadIdx.x;
    if (e >= NE) return;
    int d = g_dst32[e];
    int pos = atomicAdd(&g_cur[d], 1);
    g_sorted[pos] = ((unsigned)g_src32[e] << 20) | (unsigned)e;
}

// ---------------- GEMM (f32x2 packed): h = x @ W, a_src, a_dst --------------
// warp handles 8 rows as 4 packed row-pairs; lane = output feature.
__global__ void __launch_bounds__(256)
k_gemm(const float* __restrict__ x, const float* __restrict__ W,
       const float* __restrict__ attS, const float* __restrict__ attD) {
    __shared__ float  Wt[32 * 132];        // Wt[f][k], padded stride
    __shared__ float2 xp[8][4][128];       // [warp][pair][k] = {row2p[k], row2p+1[k]}

    int tid = threadIdx.x, wid = tid >> 5, lane = tid & 31;

    for (int i = tid; i < DIN * FF; i += 256) {
        int k = i >> 5, f = i & 31;
        Wt[f * 132 + k] = W[i];
    }

    size_t rowBase = (size_t)blockIdx.x * 64 + (size_t)wid * 8;
    const float* xg = x + rowBase * DIN;
    #pragma unroll
    for (int p = 0; p < 4; p++) {
        float4 r0 = ((const float4*)(xg + (2 * p + 0) * DIN))[lane];
        float4 r1 = ((const float4*)(xg + (2 * p + 1) * DIN))[lane];
        xp[wid][p][4 * lane + 0] = make_float2(r0.x, r1.x);
        xp[wid][p][4 * lane + 1] = make_float2(r0.y, r1.y);
        xp[wid][p][4 * lane + 2] = make_float2(r0.z, r1.z);
        xp[wid][p][4 * lane + 3] = make_float2(r0.w, r1.w);
    }
    __syncthreads();

    unsigned long long acc[4] = {0ull, 0ull, 0ull, 0ull};
    #pragma unroll 4
    for (int kc = 0; kc < 32; kc++) {
        float4 wf = *(const float4*)&Wt[lane * 132 + kc * 4];
        unsigned long long w0 = dup2(wf.x), w1 = dup2(wf.y);
        unsigned long long w2 = dup2(wf.z), w3 = dup2(wf.w);
        #pragma unroll
        for (int p = 0; p < 4; p++) {
            ulonglong2 u01 = *(const ulonglong2*)&xp[wid][p][4 * kc + 0];
            ulonglong2 u23 = *(const ulonglong2*)&xp[wid][p][4 * kc + 2];
            fma2(acc[p], u01.x, w0);
            fma2(acc[p], u01.y, w1);
            fma2(acc[p], u23.x, w2);
            fma2(acc[p], u23.y, w3);
        }
    }

    float aS = attS[lane], aD = attD[lane];
    float* hp = g_h + rowBase * FF;
    #pragma unroll
    for (int p = 0; p < 4; p++) {
        float lo, hi;
        unpack2(acc[p], lo, hi);
        hp[(2 * p + 0) * FF + lane] = lo;
        hp[(2 * p + 1) * FF + lane] = hi;
        float vs0 = lo * aS, vd0 = lo * aD, vs1 = hi * aS, vd1 = hi * aD;
        #pragma unroll
        for (int o = 16; o; o >>= 1) {
            vs0 += __shfl_xor_sync(0xFFFFFFFFu, vs0, o);
            vd0 += __shfl_xor_sync(0xFFFFFFFFu, vd0, o);
            vs1 += __shfl_xor_sync(0xFFFFFFFFu, vs1, o);
            vd1 += __shfl_xor_sync(0xFFFFFFFFu, vd1, o);
        }
        if (lane == 0) {
            g_asrc[rowBase + 2 * p + 0] = vs0;
            g_adst[rowBase + 2 * p + 0] = vd0;
            g_asrc[rowBase + 2 * p + 1] = vs1;
            g_adst[rowBase + 2 * p + 1] = vd1;
        }
    }
}

// ---------------- single-pass per-(b,dst) softmax + aggregation -------------
__device__ __forceinline__ float lrelu(float a) {
    return fmaxf(a, 0.f) + 0.2f * fminf(a, 0.f);
}

__global__ void __launch_bounds__(256)
k_edge(const float* __restrict__ eattr, const float* __restrict__ bias) {
    __shared__ float sx[8][32];
    __shared__ int   si[8][32];
    int wid = threadIdx.x >> 5, lane = threadIdx.x & 31;
    int seg = blockIdx.x * 8 + wid;                 // 0 .. NB*NN-1
    int b = seg / NN, d = seg - b * NN;

    const float* asb = g_asrc + b * NN;
    const float* eab = eattr + (size_t)b * NE;
    const float* hb  = g_h + (size_t)b * NN * FF;
    float ad = g_adst[b * NN + d];
    float c = g_c;
    int lo = g_off[d], hi = g_off[d + 1];

    // self-loop term
    float exs = __expf(lrelu(asb[d] + ad + c * g_mean[b]));
    float s = exs;
    float acc0 = exs * hb[(size_t)d * FF + lane];
    float acc1 = 0.f, acc2 = 0.f, acc3 = 0.f;

    for (int base = lo; base < hi; base += 32) {
        int m = hi - base;
        if (m > 32) m = 32;
        float ex = 0.f;
        int idx = 0;
        if (lane < m) {
            unsigned p = g_sorted[base + lane];
            int sA = p >> 20;
            int eid = p & 0xFFFFFu;
            ex = __expf(lrelu(asb[sA] + ad + c * __ldg(&eab[eid])));
            idx = sA * FF;
        }
        s += ex;
        sx[wid][lane] = ex;
        si[wid][lane] = idx;
        __syncwarp();
        int j = 0;
        for (; j + 4 <= m; j += 4) {
            int i0 = si[wid][j], i1 = si[wid][j + 1];
            int i2 = si[wid][j + 2], i3 = si[wid][j + 3];
            float e0 = sx[wid][j], e1 = sx[wid][j + 1];
            float e2 = sx[wid][j + 2], e3 = sx[wid][j + 3];
            acc0 = fmaf(e0, hb[i0 + lane], acc0);
            acc1 = fmaf(e1, hb[i1 + lane], acc1);
            acc2 = fmaf(e2, hb[i2 + lane], acc2);
            acc3 = fmaf(e3, hb[i3 + lane], acc3);
        }
        for (; j < m; ++j) {
            acc0 = fmaf(sx[wid][j], hb[si[wid][j] + lane], acc0);
        }
        __syncwarp();
    }

    // reduce s over lanes (each lane summed a disjoint subset + exs... careful:
    // every lane added exs; compensate by reducing only the edge part)
    float sedge = s - exs;
    #pragma unroll
    for (int o = 16; o; o >>= 1) sedge += __shfl_xor_sync(0xFFFFFFFFu, sedge, o);
    float stot = sedge + exs;

    float acc = (acc0 + acc1) + (acc2 + acc3);
    g_rep[((size_t)b * NN + d) * FF + lane] = acc / stot + bias[lane];
}

// ---------------- regulon pooling: out[b,r] = rep[b,r] + sum rep[b,dst] -----
__global__ void __launch_bounds__(256)
k_pool(float* __restrict__ out) {
    int wid = threadIdx.x >> 5, lane = threadIdx.x & 31;
    int seg = blockIdx.x * 8 + wid;                 // 0 .. NB*NREG-1
    int b = seg / NREG, r = seg - b * NREG;
    int lo = g_soff[r], hi = g_soff[r + 1];
    const float* repb = g_rep + (size_t)b * NN * FF;

    float a0 = repb[(size_t)r * FF + lane];
    float a1 = 0.f, a2 = 0.f, a3 = 0.f;
    for (int e0 = lo; e0 < hi; e0 += 32) {
        int rem = hi - e0;
        int m = rem < 32 ? rem : 32;
        int myd = (lane < m) ? g_dst32[e0 + lane] : 0;
        int j = 0;
        for (; j + 4 <= m; j += 4) {
            int d0 = __shfl_sync(0xFFFFFFFFu, myd, j);
            int d1 = __shfl_sync(0xFFFFFFFFu, myd, j + 1);
            int d2 = __shfl_sync(0xFFFFFFFFu, myd, j + 2);
            int d3 = __shfl_sync(0xFFFFFFFFu, myd, j + 3);
            a0 += repb[(size_t)d0 * FF + lane];
            a1 += repb[(size_t)d1 * FF + lane];
            a2 += repb[(size_t)d2 * FF + lane];
            a3 += repb[(size_t)d3 * FF + lane];
        }
        for (; j < m; ++j) {
            int dd = __shfl_sync(0xFFFFFFFFu, myd, j);
            a0 += repb[(size_t)dd * FF + lane];
        }
    }
    out[((size_t)b * NREG + r) * FF + lane] = (a0 + a1) + (a2 + a3);
}

// ---------------- launch ---------------------------------------------------
extern "C" void kernel_launch(void* const* d_in, const int* in_sizes, int n_in,
                              void* d_out, int out_size) {
    const float* x        = (const float*)d_in[0];
    const float* edgeattr = (const float*)d_in[1];
    const float* W        = (const float*)d_in[2];
    const float* att_src  = (const float*)d_in[3];
    const float* att_dst  = (const float*)d_in[4];
    const float* lin_edge = (const float*)d_in[5];
    const float* att_edge = (const float*)d_in[6];
    const float* bias     = (const float*)d_in[7];
    const void*  esrc     = d_in[8];
    const void*  edst     = d_in[9];
    float* out = (float*)d_out;

    k_prep<<<dim3(8, NB), 256>>>(edgeattr, lin_edge, att_edge, (const int*)edst);
    k_convert<<<NE / 256, 256>>>(esrc, edst);
    k_scan<<<1, 1024>>>();
    k_scatter<<<NE / 256, 256>>>();
    k_gemm<<<(NB * NN) / 64, 256>>>(x, W, att_src, att_dst);
    k_edge<<<(NB * NN) / 8, 256>>>(edgeattr, bias);
    k_pool<<<(NB * NREG) / 8, 256>>>(out);
}

// round 4
// speedup vs baseline: 1.5017x; 1.2486x over previous
#include <cuda_runtime.h>
#include <cstdint>

#define NB   16
#define NN   20000
#define NE   640000
#define NREG 2000
#define DIN  128
#define FF   32

// ---------------- scratch (device globals; no allocation allowed) ----------
__device__ float    g_h[(size_t)NB * NN * FF];       // 40.96 MB
__device__ float    g_rep[(size_t)NB * NN * FF];     // 40.96 MB
__device__ float    g_asrc[NB * NN];
__device__ float    g_adst[NB * NN];
__device__ int      g_src32[NE];
__device__ int      g_dst32[NE];
__device__ int      g_cnt[NN];
__device__ int      g_off[NN + 1];
__device__ int      g_cur[NN];
__device__ unsigned g_sorted[NE];                    // (src<<20)|eid
__device__ int      g_soff[NREG + 1];
__device__ float    g_meanpart[NB][8];
__device__ float    g_mean[NB];
__device__ float    g_c;
__device__ int      g_is64;

// ---------------- f32x2 helpers ---------------------------------------------
__device__ __forceinline__ void fma2(unsigned long long& d,
                                     unsigned long long a,
                                     unsigned long long b) {
    asm("fma.rn.f32x2 %0, %1, %2, %0;" : "+l"(d) : "l"(a), "l"(b));
}
__device__ __forceinline__ unsigned long long dup2(float w) {
    unsigned long long r;
    asm("mov.b64 %0, {%1, %1};" : "=l"(r) : "f"(w));
    return r;
}
__device__ __forceinline__ void unpack2(unsigned long long v, float& lo, float& hi) {
    asm("mov.b64 {%0, %1}, %2;" : "=f"(lo), "=f"(hi) : "l"(v));
}

// ---------------- prep: zero cnt, mean partials, scalar c, dtype detect -----
__global__ void k_prep(const float* __restrict__ eattr,
                       const float* __restrict__ lin_edge,
                       const float* __restrict__ att_edge,
                       const int* __restrict__ edge_raw) {
    int tid = threadIdx.x, bx = blockIdx.x, by = blockIdx.y;
    int lane = tid & 31, wid = tid >> 5;

    int id = (by * 8 + bx) * 256 + tid;
    if (id < NN) g_cnt[id] = 0;

    if (bx == 0 && by == 0) {
        if (wid == 0) {
            // dtype detect: int64 values < 2^31 => all odd int32 words zero
            int any = 0;
            for (int i = lane; i < 1024; i += 32)
                if ((i & 1) && edge_raw[i] != 0) any = 1;
            #pragma unroll
            for (int o = 16; o; o >>= 1) any |= __shfl_xor_sync(0xFFFFFFFFu, any, o);
            if (lane == 0) g_is64 = !any;
        } else if (wid == 1) {
            float p = lin_edge[lane] * att_edge[lane];
            #pragma unroll
            for (int o = 16; o; o >>= 1) p += __shfl_xor_sync(0xFFFFFFFFu, p, o);
            if (lane == 0) g_c = p;
        }
    }

    const float* p = eattr + (size_t)by * NE;
    float s = 0.f;
    for (int i = bx * 256 + tid; i < NE; i += 8 * 256) s += p[i];
    __shared__ float sm[8];
    #pragma unroll
    for (int o = 16; o; o >>= 1) s += __shfl_xor_sync(0xFFFFFFFFu, s, o);
    if (lane == 0) sm[wid] = s;
    __syncthreads();
    if (wid == 0) {
        s = (lane < 8) ? sm[lane] : 0.f;
        #pragma unroll
        for (int o = 4; o; o >>= 1) s += __shfl_xor_sync(0xFFFFFFFFu, s, o);
        if (lane == 0) g_meanpart[by][bx] = s;
    }
}

// ---------------- convert indices + histogram -------------------------------
__global__ void k_convert(const void* __restrict__ srcv,
                          const void* __restrict__ dstv) {
    int e = blockIdx.x * blockDim.x + threadIdx.x;
    if (e >= NE) return;
    int s, d;
    if (g_is64) {
        s = (int)((const long long*)srcv)[e];
        d = (int)((const long long*)dstv)[e];
    } else {
        s = ((const int*)srcv)[e];
        d = ((const int*)dstv)[e];
    }
    g_src32[e] = s;
    g_dst32[e] = d;
    atomicAdd(&g_cnt[d], 1);
}

// ---------------- scan + soff + mean finalize (single block, 1024 thr) ------
__global__ void k_scan() {
    __shared__ int tot[1024];
    int t = threadIdx.x;
    int base = t * 20;
    int loc[20];
    int run = 0;
    #pragma unroll
    for (int i = 0; i < 20; i++) {
        int idx = base + i;
        int v = (idx < NN) ? g_cnt[idx] : 0;
        loc[i] = run;
        run += v;
    }
    tot[t] = run;
    __syncthreads();
    for (int off = 1; off < 1024; off <<= 1) {
        int v = (t >= off) ? tot[t - off] : 0;
        __syncthreads();
        tot[t] += v;
        __syncthreads();
    }
    int excl = tot[t] - run;
    #pragma unroll
    for (int i = 0; i < 20; i++) {
        int idx = base + i;
        if (idx < NN) {
            int o = excl + loc[i];
            g_off[idx] = o;
            g_cur[idx] = o;
        }
    }
    if (t == 1023) g_off[NN] = tot[1023];

    for (int r = t; r <= NREG; r += 1024) {
        int lo = 0, hi = NE;
        while (lo < hi) {
            int mid = (lo + hi) >> 1;
            if (g_src32[mid] < r) lo = mid + 1; else hi = mid;
        }
        g_soff[r] = lo;
    }

    if (t < NB) {
        float s = 0.f;
        #pragma unroll
        for (int i = 0; i < 8; i++) s += g_meanpart[t][i];
        g_mean[t] = s * (1.0f / NE);
    }
}

__global__ void k_scatter() {
    int e = blockIdx.x * blockDim.x + threadIdx.x;
    if (e >= NE) return;
    int d = g_dst32[e];
    int pos = atomicAdd(&g_cur[d], 1);
    g_sorted[pos] = ((unsigned)g_src32[e] << 20) | (unsigned)e;
}

// ---------------- GEMM (f32x2 packed): h = x @ W, a_src, a_dst --------------
__global__ void __launch_bounds__(256)
k_gemm(const float* __restrict__ x, const float* __restrict__ W,
       const float* __restrict__ attS, const float* __restrict__ attD) {
    __shared__ float  Wt[32 * 132];
    __shared__ float2 xp[8][4][128];

    int tid = threadIdx.x, wid = tid >> 5, lane = tid & 31;

    for (int i = tid; i < DIN * FF; i += 256) {
        int k = i >> 5, f = i & 31;
        Wt[f * 132 + k] = W[i];
    }

    size_t rowBase = (size_t)blockIdx.x * 64 + (size_t)wid * 8;
    const float* xg = x + rowBase * DIN;
    #pragma unroll
    for (int p = 0; p < 4; p++) {
        float4 r0 = ((const float4*)(xg + (2 * p + 0) * DIN))[lane];
        float4 r1 = ((const float4*)(xg + (2 * p + 1) * DIN))[lane];
        xp[wid][p][4 * lane + 0] = make_float2(r0.x, r1.x);
        xp[wid][p][4 * lane + 1] = make_float2(r0.y, r1.y);
        xp[wid][p][4 * lane + 2] = make_float2(r0.z, r1.z);
        xp[wid][p][4 * lane + 3] = make_float2(r0.w, r1.w);
    }
    __syncthreads();

    unsigned long long acc[4] = {0ull, 0ull, 0ull, 0ull};
    #pragma unroll 4
    for (int kc = 0; kc < 32; kc++) {
        float4 wf = *(const float4*)&Wt[lane * 132 + kc * 4];
        unsigned long long w0 = dup2(wf.x), w1 = dup2(wf.y);
        unsigned long long w2 = dup2(wf.z), w3 = dup2(wf.w);
        #pragma unroll
        for (int p = 0; p < 4; p++) {
            ulonglong2 u01 = *(const ulonglong2*)&xp[wid][p][4 * kc + 0];
            ulonglong2 u23 = *(const ulonglong2*)&xp[wid][p][4 * kc + 2];
            fma2(acc[p], u01.x, w0);
            fma2(acc[p], u01.y, w1);
            fma2(acc[p], u23.x, w2);
            fma2(acc[p], u23.y, w3);
        }
    }

    float aS = attS[lane], aD = attD[lane];
    float* hp = g_h + rowBase * FF;
    #pragma unroll
    for (int p = 0; p < 4; p++) {
        float lo, hi;
        unpack2(acc[p], lo, hi);
        hp[(2 * p + 0) * FF + lane] = lo;
        hp[(2 * p + 1) * FF + lane] = hi;
        float vs0 = lo * aS, vd0 = lo * aD, vs1 = hi * aS, vd1 = hi * aD;
        #pragma unroll
        for (int o = 16; o; o >>= 1) {
            vs0 += __shfl_xor_sync(0xFFFFFFFFu, vs0, o);
            vd0 += __shfl_xor_sync(0xFFFFFFFFu, vd0, o);
            vs1 += __shfl_xor_sync(0xFFFFFFFFu, vs1, o);
            vd1 += __shfl_xor_sync(0xFFFFFFFFu, vd1, o);
        }
        if (lane == 0) {
            g_asrc[rowBase + 2 * p + 0] = vs0;
            g_adst[rowBase + 2 * p + 0] = vd0;
            g_asrc[rowBase + 2 * p + 1] = vs1;
            g_adst[rowBase + 2 * p + 1] = vd1;
        }
    }
}

// ---------------- single-pass per-(b,dst) softmax + aggregation -------------
// 4 rows per LDG.128: lane = (row-group g4 = lane>>3, feature-quad q = lane&7)
__device__ __forceinline__ float lrelu(float a) {
    return fmaxf(a, 0.f) + 0.2f * fminf(a, 0.f);
}

__global__ void __launch_bounds__(256)
k_edge(const float* __restrict__ eattr, const float* __restrict__ bias) {
    int wid = threadIdx.x >> 5, lane = threadIdx.x & 31;
    int seg = blockIdx.x * 8 + wid;                 // 0 .. NB*NN-1
    int b = seg / NN, d = seg - b * NN;

    const float* asb = g_asrc + b * NN;
    const float* eab = eattr + (size_t)b * NE;
    const float* hb  = g_h + (size_t)b * NN * FF;
    float ad = g_adst[b * NN + d];
    float c = g_c;
    int lo = g_off[d], hi = g_off[d + 1];
    int q = lane & 7, g4 = lane >> 3;

    float4 acc = make_float4(0.f, 0.f, 0.f, 0.f);
    float ssum = 0.f;

    for (int base = lo; base < hi; base += 32) {
        int m = hi - base;
        if (m > 32) m = 32;
        float ex = 0.f;
        int idx = d * FF;                            // safe default row
        if (lane < m) {
            unsigned p = g_sorted[base + lane];
            int sA = p >> 20;
            int eid = p & 0xFFFFFu;
            ex = __expf(lrelu(asb[sA] + ad + c * __ldg(&eab[eid])));
            idx = sA * FF;
        }
        ssum += ex;
        for (int g = 0; g < m; g += 8) {
            int j0 = g + g4, j1 = g + 4 + g4;        // j1 <= 31 always
            float e0 = __shfl_sync(0xFFFFFFFFu, ex, j0);
            int   i0 = __shfl_sync(0xFFFFFFFFu, idx, j0);
            float e1 = __shfl_sync(0xFFFFFFFFu, ex, j1);
            int   i1 = __shfl_sync(0xFFFFFFFFu, idx, j1);
            float4 v0 = *(const float4*)(hb + i0 + q * 4);
            float4 v1 = *(const float4*)(hb + i1 + q * 4);
            acc.x = fmaf(e0, v0.x, acc.x);
            acc.y = fmaf(e0, v0.y, acc.y);
            acc.z = fmaf(e0, v0.z, acc.z);
            acc.w = fmaf(e0, v0.w, acc.w);
            acc.x = fmaf(e1, v1.x, acc.x);
            acc.y = fmaf(e1, v1.y, acc.y);
            acc.z = fmaf(e1, v1.z, acc.z);
            acc.w = fmaf(e1, v1.w, acc.w);
        }
    }

    // softmax denominator
    float exs = __expf(lrelu(asb[d] + ad + c * g_mean[b]));
    #pragma unroll
    for (int o = 16; o; o >>= 1) ssum += __shfl_xor_sync(0xFFFFFFFFu, ssum, o);
    float inv = 1.f / (ssum + exs);

    // reduce row-group partials (lanes l, l^8, l^16, l^24 share feature-quad)
    #pragma unroll
    for (int o = 8; o <= 16; o <<= 1) {
        acc.x += __shfl_xor_sync(0xFFFFFFFFu, acc.x, o);
        acc.y += __shfl_xor_sync(0xFFFFFFFFu, acc.y, o);
        acc.z += __shfl_xor_sync(0xFFFFFFFFu, acc.z, o);
        acc.w += __shfl_xor_sync(0xFFFFFFFFu, acc.w, o);
    }

    if (lane < 8) {
        float4 hs = *(const float4*)(hb + d * FF + q * 4);
        float4 bq = *(const float4*)(bias + q * 4);
        float4 r;
        r.x = fmaf(exs, hs.x, acc.x) * inv + bq.x;
        r.y = fmaf(exs, hs.y, acc.y) * inv + bq.y;
        r.z = fmaf(exs, hs.z, acc.z) * inv + bq.z;
        r.w = fmaf(exs, hs.w, acc.w) * inv + bq.w;
        *(float4*)(g_rep + ((size_t)b * NN + d) * FF + q * 4) = r;
    }
}

// ---------------- regulon pooling: out[b,r] = rep[b,r] + sum rep[b,dst] -----
__global__ void __launch_bounds__(256)
k_pool(float* __restrict__ out) {
    int wid = threadIdx.x >> 5, lane = threadIdx.x & 31;
    int seg = blockIdx.x * 8 + wid;                 // 0 .. NB*NREG-1
    int b = seg / NREG, r = seg - b * NREG;
    int lo = g_soff[r], hi = g_soff[r + 1];
    const float* repb = g_rep + (size_t)b * NN * FF;
    int q = lane & 7, g4 = lane >> 3;

    float4 a0 = make_float4(0.f, 0.f, 0.f, 0.f);
    float4 a1 = make_float4(0.f, 0.f, 0.f, 0.f);

    for (int base = lo; base < hi; base += 32) {
        int m = hi - base;
        if (m > 32) m = 32;
        int idx = (lane < m) ? g_dst32[base + lane] * FF : -1;
        for (int g = 0; g < m; g += 8) {
            int i0 = __shfl_sync(0xFFFFFFFFu, idx, g + g4);
            int i1 = __shfl_sync(0xFFFFFFFFu, idx, g + 4 + g4);
            if (i0 >= 0) {
                float4 v = *(const float4*)(repb + i0 + q * 4);
                a0.x += v.x; a0.y += v.y; a0.z += v.z; a0.w += v.w;
            }
            if (i1 >= 0) {
                float4 v = *(const float4*)(repb + i1 + q * 4);
                a1.x += v.x; a1.y += v.y; a1.z += v.z; a1.w += v.w;
            }
        }
    }
    a0.x += a1.x; a0.y += a1.y; a0.z += a1.z; a0.w += a1.w;

    #pragma unroll
    for (int o = 8; o <= 16; o <<= 1) {
        a0.x += __shfl_xor_sync(0xFFFFFFFFu, a0.x, o);
        a0.y += __shfl_xor_sync(0xFFFFFFFFu, a0.y, o);
        a0.z += __shfl_xor_sync(0xFFFFFFFFu, a0.z, o);
        a0.w += __shfl_xor_sync(0xFFFFFFFFu, a0.w, o);
    }

    if (lane < 8) {
        float4 self = *(const float4*)(repb + (size_t)r * FF + q * 4);
        float4 o4;
        o4.x = a0.x + self.x;
        o4.y = a0.y + self.y;
        o4.z = a0.z + self.z;
        o4.w = a0.w + self.w;
        *(float4*)(out + ((size_t)b * NREG + r) * FF + q * 4) = o4;
    }
}

// ---------------- launch ---------------------------------------------------
extern "C" void kernel_launch(void* const* d_in, const int* in_sizes, int n_in,
                              void* d_out, int out_size) {
    const float* x        = (const float*)d_in[0];
    const float* edgeattr = (const float*)d_in[1];
    const float* W        = (const float*)d_in[2];
    const float* att_src  = (const float*)d_in[3];
    const float* att_dst  = (const float*)d_in[4];
    const float* lin_edge = (const float*)d_in[5];
    const float* att_edge = (const float*)d_in[6];
    const float* bias     = (const float*)d_in[7];
    const void*  esrc     = d_in[8];
    const void*  edst     = d_in[9];
    float* out = (float*)d_out;

    k_prep<<<dim3(8, NB), 256>>>(edgeattr, lin_edge, att_edge, (const int*)edst);
    k_convert<<<NE / 256, 256>>>(esrc, edst);
    k_scan<<<1, 1024>>>();
    k_scatter<<<NE / 256, 256>>>();
    k_gemm<<<(NB * NN) / 64, 256>>>(x, W, att_src, att_dst);
    k_edge<<<(NB * NN) / 8, 256>>>(edgeattr, bias);
    k_pool<<<(NB * NREG) / 8, 256>>>(out);
}